// round 13
// baseline (speedup 1.0000x reference)
#include <cuda_runtime.h>
#include <cuda_bf16.h>
#include <math.h>

#define BB 4
#define NN 4096
#define KK 16

typedef unsigned long long ull;
typedef unsigned int uint;

// scratch (device globals: allocation-free per harness rules)
__device__ float g_qkv[BB * NN * 192];            // point-major: [b][n][192]
__device__ int   g_idx[BB * NN * KK];             // [b][n][k]
__device__ float g_pe[(size_t)BB * NN * KK * 64]; // [gp][64]

// ============================ mma.sync helpers =============================
__device__ __forceinline__ uint smem_u32(const void* p) {
    uint a;
    asm("{ .reg .u64 t; cvta.to.shared.u64 t, %1; cvt.u32.u64 %0, t; }"
        : "=r"(a) : "l"(p));
    return a;
}
__device__ __forceinline__ void ldsm4(uint* r, uint addr) {
    asm volatile("ldmatrix.sync.aligned.m8n8.x4.shared.b16 {%0,%1,%2,%3}, [%4];"
                 : "=r"(r[0]), "=r"(r[1]), "=r"(r[2]), "=r"(r[3]) : "r"(addr));
}
__device__ __forceinline__ void mma_bf16(float* d, const uint* a, const uint* b) {
    asm volatile(
        "mma.sync.aligned.m16n8k16.row.col.f32.bf16.bf16.f32 "
        "{%0,%1,%2,%3},{%4,%5,%6,%7},{%8,%9},{%0,%1,%2,%3};"
        : "+f"(d[0]), "+f"(d[1]), "+f"(d[2]), "+f"(d[3])
        : "r"(a[0]), "r"(a[1]), "r"(a[2]), "r"(a[3]), "r"(b[0]), "r"(b[1]));
}
__device__ __forceinline__ uint bf2(float a, float b) {
    unsigned short ha = __bfloat16_as_ushort(__float2bfloat16_rn(a));
    unsigned short hb = __bfloat16_as_ushort(__float2bfloat16_rn(b));
    return (uint)ha | ((uint)hb << 16);
}
__device__ __forceinline__ float bfres(float a) {
    return a - __bfloat162float(__float2bfloat16_rn(a));
}
// A-fragment ldmatrix.x4 address (16x16 tile at (row0, byte L0), row width W)
__device__ __forceinline__ uint afrag_addr(uint base, int W, int row0, int L0, int lane) {
    int row = row0 + (lane & 7) + ((lane >> 3) & 1) * 8;
    int l = L0 + (lane >> 4) * 16;
    return base + row * W + (l ^ ((row & 7) << 4));
}
// B-fragment ldmatrix.x4 address (two n-tiles n0..n0+15, k16 at byte L0)
__device__ __forceinline__ uint bfrag_addr(uint base, int W, int n0, int L0, int lane) {
    int row = n0 + (lane & 7) + (lane >> 4) * 8;
    int l = L0 + ((lane >> 3) & 1) * 16;
    return base + row * W + (l ^ ((row & 7) << 4));
}

// fused kernel smem byte offsets
#define OFF_W1H 0u        /* [256 r][64 k] bf16 swz, 32768 */
#define OFF_W1L 32768u
#define OFF_W2H 65536u    /* [64 o][256 k] bf16 swz, 32768 */
#define OFF_W2L 98304u
#define OFF_HALF0 131072u /* per-half region, 49152 each */
#define HALF_STRIDE 49152u
#define OFF_B1  229376u
#define OFF_B2  230400u
#define OFF_SJ  230656u   /* int[2][64] */
#define SMEM_TC 231168u

// pos kernel smem byte offsets
#define POFF_AH  0u
#define POFF_AL  32768u
#define POFF_WH  65536u
#define POFF_WL  73728u
#define POFF_WP1 81920u
#define POFF_BP1 82688u
#define POFF_BP2 82944u
#define SMEM_POS 83200u

// ---------------------------------------------------------------------------
// Kernel 1: combined KNN (blocks 0..511) + QKV (blocks 512..767).
// KNN: 256 threads = 32 queries x 8 candidate-partitions (512 cand each),
// parallel-select insert, shuffle tournament merge (strides 1,2,4).
// ---------------------------------------------------------------------------
__device__ __forceinline__ void topk_insert(float d2, int m, float bd[16], int bi[16]) {
    bool p[16];
#pragma unroll
    for (int i = 0; i < 16; ++i) p[i] = d2 < bd[i];
#pragma unroll
    for (int i = 15; i > 0; --i) {
        bd[i] = p[i] ? (p[i - 1] ? bd[i - 1] : d2) : bd[i];
        bi[i] = p[i] ? (p[i - 1] ? bi[i - 1] : m) : bi[i];
    }
    if (p[0]) { bd[0] = d2; bi[0] = m; }
}

__global__ void knn_qkv_kernel(const float* __restrict__ xyz,
                               const float* __restrict__ points,
                               const float* __restrict__ w_qkv) {
    extern __shared__ float sm[];
    int t = threadIdx.x;  // 256

    if (blockIdx.x < 512) {
        // ================= KNN: 8 partitions, shuffle merge =================
        float4* c4 = (float4*)sm;          // 4096 float4 = 65536 B

        int b = blockIdx.x >> 7;           // 128 tiles per batch
        int tile = blockIdx.x & 127;
        const float* xb = xyz + (size_t)b * 3 * NN;

        for (int m = t; m < NN; m += 256) {
            float x = xb[m], y = xb[NN + m], z = xb[2 * NN + m];
            c4[m] = make_float4(x, y, z, x * x + y * y + z * z);
        }
        __syncthreads();

        int q = tile * 32 + (t >> 3);
        int p = t & 7;
        float4 qc = c4[q];
        float qx = qc.x, qy = qc.y, qz = qc.z, sqq = qc.w;

        float bd[16]; int bi[16];
#pragma unroll
        for (int i = 0; i < 16; ++i) { bd[i] = 3.4e38f; bi[i] = -1; }

        int m0 = p * 512;
        for (int m = m0; m < m0 + 512; m += 2) {
            float4 ca = c4[m], cb = c4[m + 1];
            float dot0 = fmaf(qx, ca.x, fmaf(qy, ca.y, qz * ca.z));
            float dot1 = fmaf(qx, cb.x, fmaf(qy, cb.y, qz * cb.z));
            float d20 = fmaf(-2.f, dot0, sqq + ca.w);
            float d21 = fmaf(-2.f, dot1, sqq + cb.w);
            if (d20 < bd[15]) topk_insert(d20, m, bd, bi);
            if (d21 < bd[15]) topk_insert(d21, m + 1, bd, bi);
        }

        // ---- tournament merge via shuffles: strides 1, 2, 4 ----
#pragma unroll
        for (int s = 1; s <= 4; s <<= 1) {
            int mask2 = 2 * s - 1;
#pragma unroll 1
            for (int e = 0; e < 16; ++e) {
                float od = __shfl_down_sync(0xFFFFFFFFu, bd[e], s);
                int   oi = __shfl_down_sync(0xFFFFFFFFu, bi[e], s);
                bool recv = ((p & mask2) == 0) && (od < bd[15]);
                if (__all_sync(0xFFFFFFFFu, !recv)) break;  // lists ascending
                if (recv) topk_insert(od, oi, bd, bi);
            }
        }

        if (p == 0) {
            int* op = g_idx + ((size_t)(b * NN + q)) * KK;
#pragma unroll
            for (int i = 0; i < 16; ++i) op[i] = bi[i];
        }
    } else {
        // ================= QKV (R8-verified version) =================
        int bid = blockIdx.x - 512;
        float* sw = sm;
        {
            const float4* a = (const float4*)w_qkv;
            float4* d = (float4*)sw;
            for (int i = t; i < 3072; i += 256) d[i] = a[i];
        }
        __syncthreads();
        int b = bid >> 6;
        int n = ((bid & 63) << 6) + (t & 63);
        int oh = t >> 6;

        float4 p4[16];
        const float* pb = points + (size_t)b * 64 * NN + n;
#pragma unroll
        for (int d4 = 0; d4 < 16; ++d4) {
            p4[d4].x = pb[(size_t)(4 * d4 + 0) * NN];
            p4[d4].y = pb[(size_t)(4 * d4 + 1) * NN];
            p4[d4].z = pb[(size_t)(4 * d4 + 2) * NN];
            p4[d4].w = pb[(size_t)(4 * d4 + 3) * NN];
        }
        float* outp = g_qkv + ((size_t)(b * NN + n)) * 192 + oh * 48;
        const float* swh = sw + oh * 48 * 64;
        for (int ob = 0; ob < 12; ++ob) {
            float a0 = 0.f, a1 = 0.f, a2 = 0.f, a3 = 0.f;
            const float4* w0 = (const float4*)(swh + (4 * ob + 0) * 64);
            const float4* w1 = (const float4*)(swh + (4 * ob + 1) * 64);
            const float4* w2 = (const float4*)(swh + (4 * ob + 2) * 64);
            const float4* w3 = (const float4*)(swh + (4 * ob + 3) * 64);
#pragma unroll
            for (int d4 = 0; d4 < 16; ++d4) {
                float4 pv = p4[d4];
                float4 wa = w0[d4], wb = w1[d4], wc = w2[d4], wd = w3[d4];
                a0 = fmaf(wa.x, pv.x, a0); a0 = fmaf(wa.y, pv.y, a0);
                a0 = fmaf(wa.z, pv.z, a0); a0 = fmaf(wa.w, pv.w, a0);
                a1 = fmaf(wb.x, pv.x, a1); a1 = fmaf(wb.y, pv.y, a1);
                a1 = fmaf(wb.z, pv.z, a1); a1 = fmaf(wb.w, pv.w, a1);
                a2 = fmaf(wc.x, pv.x, a2); a2 = fmaf(wc.y, pv.y, a2);
                a2 = fmaf(wc.z, pv.z, a2); a2 = fmaf(wc.w, pv.w, a2);
                a3 = fmaf(wd.x, pv.x, a3); a3 = fmaf(wd.y, pv.y, a3);
                a3 = fmaf(wd.z, pv.z, a3); a3 = fmaf(wd.w, pv.w, a3);
            }
            *(float4*)(outp + 4 * ob) = make_float4(a0, a1, a2, a3);
        }
    }
}

// ---------------------------------------------------------------------------
// Kernel 3: pos-MLP -> g_pe (unchanged — verified).
// ---------------------------------------------------------------------------
__global__ void __launch_bounds__(256, 2)
pos_kernel(const float* __restrict__ xyz,
           const float* __restrict__ w_pos1, const float* __restrict__ b_pos1,
           const float* __restrict__ w_pos2, const float* __restrict__ b_pos2) {
    extern __shared__ char psm[];
    uint sbase = smem_u32(psm);
    int t = threadIdx.x, wid = t >> 5, lane = t & 31;
    float* wp1 = (float*)(psm + POFF_WP1);
    float* bp1 = (float*)(psm + POFF_BP1);
    float* bp2 = (float*)(psm + POFF_BP2);

    for (int i = t; i < 1024; i += 256) {
        float4 f = ((const float4*)w_pos2)[i];
        int o = i >> 4, h = (i * 4) & 63;
        int swl = (h * 2) ^ ((o & 7) << 4);
        *(uint*)(psm + POFF_WH + o * 128 + swl)     = bf2(f.x, f.y);
        *(uint*)(psm + POFF_WH + o * 128 + swl + 4) = bf2(f.z, f.w);
        *(uint*)(psm + POFF_WL + o * 128 + swl)     = bf2(bfres(f.x), bfres(f.y));
        *(uint*)(psm + POFF_WL + o * 128 + swl + 4) = bf2(bfres(f.z), bfres(f.w));
    }
    if (t < 192) wp1[t] = w_pos1[t];
    if (t < 64) { bp1[t] = b_pos1[t]; bp2[t] = b_pos2[t]; }

    size_t gp0 = (size_t)blockIdx.x * 256;
    int b = (int)(gp0 >> 16);

    {
        size_t gp = gp0 + t;
        int n = (int)((gp >> 4) & 4095);
        int j = g_idx[gp];
        const float* xb = xyz + (size_t)b * 3 * NN;
        float gx0 = xb[n] - xb[j];
        float gx1 = xb[NN + n] - xb[NN + j];
        float gx2 = xb[2 * NN + n] - xb[2 * NN + j];
        __syncthreads();
        int rowb = t * 128;
        int sx = (t & 7) << 4;
#pragma unroll
        for (int h = 0; h < 64; h += 2) {
            float v0 = fmaf(wp1[h * 3 + 2], gx2,
                       fmaf(wp1[h * 3 + 1], gx1,
                       fmaf(wp1[h * 3 + 0], gx0, bp1[h])));
            float v1 = fmaf(wp1[h * 3 + 5], gx2,
                       fmaf(wp1[h * 3 + 4], gx1,
                       fmaf(wp1[h * 3 + 3], gx0, bp1[h + 1])));
            v0 = fmaxf(v0, 0.f); v1 = fmaxf(v1, 0.f);
            int swl = (h * 2) ^ sx;
            *(uint*)(psm + POFF_AH + rowb + swl) = bf2(v0, v1);
            *(uint*)(psm + POFF_AL + rowb + swl) = bf2(bfres(v0), bfres(v1));
        }
    }
    __syncthreads();

    {
        int p0 = wid * 32;
        float d[2][8][4];
#pragma unroll
        for (int mt = 0; mt < 2; ++mt)
#pragma unroll
            for (int nt = 0; nt < 8; ++nt)
#pragma unroll
                for (int e = 0; e < 4; ++e) d[mt][nt][e] = 0.f;

#pragma unroll
        for (int ks = 0; ks < 4; ++ks) {
            int L0 = ks * 32;
            uint aH[2][4], aL[2][4], bH[4][4], bL[4][4];
            ldsm4(aH[0], afrag_addr(sbase + POFF_AH, 128, p0, L0, lane));
            ldsm4(aH[1], afrag_addr(sbase + POFF_AH, 128, p0 + 16, L0, lane));
            ldsm4(aL[0], afrag_addr(sbase + POFF_AL, 128, p0, L0, lane));
            ldsm4(aL[1], afrag_addr(sbase + POFF_AL, 128, p0 + 16, L0, lane));
#pragma unroll
            for (int g = 0; g < 4; ++g) {
                ldsm4(bH[g], bfrag_addr(sbase + POFF_WH, 128, g * 16, L0, lane));
                ldsm4(bL[g], bfrag_addr(sbase + POFF_WL, 128, g * 16, L0, lane));
            }
#pragma unroll
            for (int mt = 0; mt < 2; ++mt)
#pragma unroll
                for (int nt = 0; nt < 8; ++nt) {
                    const uint* bh = &bH[nt >> 1][(nt & 1) * 2];
                    const uint* bl = &bL[nt >> 1][(nt & 1) * 2];
                    mma_bf16(d[mt][nt], aH[mt], bh);
                    mma_bf16(d[mt][nt], aH[mt], bl);
                    mma_bf16(d[mt][nt], aL[mt], bh);
                }
        }
#pragma unroll
        for (int mt = 0; mt < 2; ++mt) {
            int cA = p0 + mt * 16 + (lane >> 2);
            int cB = cA + 8;
#pragma unroll
            for (int nt = 0; nt < 8; ++nt) {
                int o = nt * 8 + (lane & 3) * 2;
                float b0v = bp2[o], b1v = bp2[o + 1];
                *(float2*)(g_pe + (gp0 + cA) * 64 + o) =
                    make_float2(d[mt][nt][0] + b0v, d[mt][nt][1] + b1v);
                *(float2*)(g_pe + (gp0 + cB) * 64 + o) =
                    make_float2(d[mt][nt][2] + b0v, d[mt][nt][3] + b1v);
            }
        }
    }
}

// ---------------------------------------------------------------------------
// Kernel 4: fused att-MLP via mma.sync — split-block (R9-verified, 233us).
// ---------------------------------------------------------------------------
__global__ void __launch_bounds__(512, 1)
fused_mma_kernel(const float* __restrict__ w_att1, const float* __restrict__ b_att1,
                 const float* __restrict__ w_att2, const float* __restrict__ b_att2,
                 float* __restrict__ out) {
    extern __shared__ char smem[];
    uint sbase = smem_u32(smem);
    int t = threadIdx.x, wid = t >> 5, lane = t & 31;
    float* sb1 = (float*)(smem + OFF_B1);
    float* sb2 = (float*)(smem + OFF_B2);

    for (int i = t; i < 4096; i += 512) {       // w1 [256][64]
        float4 f = ((const float4*)w_att1)[i];
        int r = i >> 4, k = (i * 4) & 63;
        int swl = ((k * 2) ^ ((r & 7) << 4));
        *(uint*)(smem + OFF_W1H + r * 128 + swl)     = bf2(f.x, f.y);
        *(uint*)(smem + OFF_W1H + r * 128 + swl + 4) = bf2(f.z, f.w);
        *(uint*)(smem + OFF_W1L + r * 128 + swl)     = bf2(bfres(f.x), bfres(f.y));
        *(uint*)(smem + OFF_W1L + r * 128 + swl + 4) = bf2(bfres(f.z), bfres(f.w));
    }
    for (int i = t; i < 4096; i += 512) {       // w2 [64][256]
        float4 f = ((const float4*)w_att2)[i];
        int o = i >> 6, k = (i * 4) & 255;
        int swl = ((k * 2) ^ ((o & 7) << 4));
        *(uint*)(smem + OFF_W2H + o * 512 + swl)     = bf2(f.x, f.y);
        *(uint*)(smem + OFF_W2H + o * 512 + swl + 4) = bf2(f.z, f.w);
        *(uint*)(smem + OFF_W2L + o * 512 + swl)     = bf2(bfres(f.x), bfres(f.y));
        *(uint*)(smem + OFF_W2L + o * 512 + swl + 4) = bf2(bfres(f.z), bfres(f.w));
    }
    if (t < 256) sb1[t] = b_att1[t];
    if (t < 64) sb2[t] = b_att2[t];
    __syncthreads();

    const int half = wid >> 3;
    const int th = t & 255;
    const int wh = wid & 7;
    const uint HB = OFF_HALF0 + (uint)half * HALF_STRIDE;
    const uint OXH = HB, OXL = HB + 8192u, OHH = HB + 16384u, OHL = HB + 32768u;
    const uint OSIM = HB + 16384u;
    int* sj = (int*)(smem + OFF_SJ) + half * 64;

    const int c0 = (wh & 1) * 32;
    const int r0w = (wh >> 1) * 32;
    const int o0 = (wh >> 1) * 16;

    int b = blockIdx.x >> 8;
    int nb = ((blockIdx.x & 255) << 4) + half * 8;

#define BARH() asm volatile("bar.sync %0, 256;" :: "r"(half + 1) : "memory")

    for (int st = 0; st < 2; ++st) {
        int n0 = nb + st * 4;

        {
            int c = th >> 2;
            int dq = (th & 3) << 4;
            int qi = c >> 4;
            int j = g_idx[((size_t)(b * NN + n0 + qi)) * KK + (c & 15)];
            if ((th & 3) == 0) sj[c] = j;
            const float* kp = g_qkv + ((size_t)(b * NN + j)) * 192 + 64 + dq;
            const float* qp = g_qkv + ((size_t)(b * NN + n0 + qi)) * 192 + dq;
            const float* pp = g_pe + ((size_t)b * 65536 + (size_t)n0 * 16 + c) * 64 + dq;
            int rowb = c * 128;
            int sx = (c & 7) << 4;
#pragma unroll
            for (int i = 0; i < 4; ++i) {
                float4 kk = *(const float4*)(kp + 4 * i);
                float4 qq = *(const float4*)(qp + 4 * i);
                float4 pe = *(const float4*)(pp + 4 * i);
                float x0 = qq.x - kk.x + pe.x;
                float x1 = qq.y - kk.y + pe.y;
                float x2 = qq.z - kk.z + pe.z;
                float x3 = qq.w - kk.w + pe.w;
                int swl = ((dq + 4 * i) * 2) ^ sx;
                *(uint*)(smem + OXH + rowb + swl)     = bf2(x0, x1);
                *(uint*)(smem + OXH + rowb + swl + 4) = bf2(x2, x3);
                *(uint*)(smem + OXL + rowb + swl)     = bf2(bfres(x0), bfres(x1));
                *(uint*)(smem + OXL + rowb + swl + 4) = bf2(bfres(x2), bfres(x3));
            }
        }
        BARH();

        float dF[2][2][4];
#pragma unroll
        for (int mt = 0; mt < 2; ++mt)
#pragma unroll
            for (int nt = 0; nt < 2; ++nt)
#pragma unroll
                for (int e = 0; e < 4; ++e) dF[mt][nt][e] = 0.f;

        for (int ph = 0; ph < 2; ++ph) {
            float dE[2][4][4];
#pragma unroll
            for (int mt = 0; mt < 2; ++mt)
#pragma unroll
                for (int nt = 0; nt < 4; ++nt)
#pragma unroll
                    for (int e = 0; e < 4; ++e) dE[mt][nt][e] = 0.f;

            int nbse = ph * 128 + r0w;
#pragma unroll
            for (int ks = 0; ks < 4; ++ks) {
                int L0 = ks * 32;
                uint aH[2][4], aL[2][4], bH[2][4], bL[2][4];
                ldsm4(aH[0], afrag_addr(sbase + OXH, 128, c0, L0, lane));
                ldsm4(aH[1], afrag_addr(sbase + OXH, 128, c0 + 16, L0, lane));
                ldsm4(aL[0], afrag_addr(sbase + OXL, 128, c0, L0, lane));
                ldsm4(aL[1], afrag_addr(sbase + OXL, 128, c0 + 16, L0, lane));
                ldsm4(bH[0], bfrag_addr(sbase + OFF_W1H, 128, nbse, L0, lane));
                ldsm4(bH[1], bfrag_addr(sbase + OFF_W1H, 128, nbse + 16, L0, lane));
                ldsm4(bL[0], bfrag_addr(sbase + OFF_W1L, 128, nbse, L0, lane));
                ldsm4(bL[1], bfrag_addr(sbase + OFF_W1L, 128, nbse + 16, L0, lane));
#pragma unroll
                for (int mt = 0; mt < 2; ++mt)
#pragma unroll
                    for (int nt = 0; nt < 4; ++nt) {
                        const uint* bh = &bH[nt >> 1][(nt & 1) * 2];
                        const uint* bl = &bL[nt >> 1][(nt & 1) * 2];
                        mma_bf16(dE[mt][nt], aH[mt], bh);
                        mma_bf16(dE[mt][nt], aH[mt], bl);
                        mma_bf16(dE[mt][nt], aL[mt], bh);
                    }
            }
#pragma unroll
            for (int mt = 0; mt < 2; ++mt) {
                int cA = c0 + mt * 16 + (lane >> 2);
                int cB = cA + 8;
#pragma unroll
                for (int nt = 0; nt < 4; ++nt) {
                    int rl = r0w + nt * 8 + (lane & 3) * 2;
                    int rg = ph * 128 + rl;
                    float b0v = sb1[rg], b1v = sb1[rg + 1];
                    float v0 = fmaxf(dE[mt][nt][0] + b0v, 0.f);
                    float v1 = fmaxf(dE[mt][nt][1] + b1v, 0.f);
                    float v2 = fmaxf(dE[mt][nt][2] + b0v, 0.f);
                    float v3 = fmaxf(dE[mt][nt][3] + b1v, 0.f);
                    int lA = (rl * 2) ^ ((cA & 7) << 4);
                    int lB = (rl * 2) ^ ((cB & 7) << 4);
                    *(uint*)(smem + OHH + cA * 256 + lA) = bf2(v0, v1);
                    *(uint*)(smem + OHL + cA * 256 + lA) = bf2(bfres(v0), bfres(v1));
                    *(uint*)(smem + OHH + cB * 256 + lB) = bf2(v2, v3);
                    *(uint*)(smem + OHL + cB * 256 + lB) = bf2(bfres(v2), bfres(v3));
                }
            }
            BARH();

#pragma unroll
            for (int ks = 0; ks < 8; ++ks) {
                int L0 = ks * 32;
                int L0w = ph * 256 + L0;
                uint aH[2][4], aL[2][4], bH[4], bL[4];
                ldsm4(aH[0], afrag_addr(sbase + OHH, 256, c0, L0, lane));
                ldsm4(aH[1], afrag_addr(sbase + OHH, 256, c0 + 16, L0, lane));
                ldsm4(aL[0], afrag_addr(sbase + OHL, 256, c0, L0, lane));
                ldsm4(aL[1], afrag_addr(sbase + OHL, 256, c0 + 16, L0, lane));
                ldsm4(bH, bfrag_addr(sbase + OFF_W2H, 512, o0, L0w, lane));
                ldsm4(bL, bfrag_addr(sbase + OFF_W2L, 512, o0, L0w, lane));
#pragma unroll
                for (int mt = 0; mt < 2; ++mt)
#pragma unroll
                    for (int nt = 0; nt < 2; ++nt) {
                        const uint* bh = &bH[nt * 2];
                        const uint* bl = &bL[nt * 2];
                        mma_bf16(dF[mt][nt], aH[mt], bh);
                        mma_bf16(dF[mt][nt], aH[mt], bl);
                        mma_bf16(dF[mt][nt], aL[mt], bh);
                    }
            }
            BARH();
        }

        {
            float* simf = (float*)(smem + OSIM);
#pragma unroll
            for (int mt = 0; mt < 2; ++mt) {
                int cA = c0 + mt * 16 + (lane >> 2);
                int cB = cA + 8;
#pragma unroll
                for (int nt = 0; nt < 2; ++nt) {
                    int o = o0 + nt * 8 + (lane & 3) * 2;
                    float b0v = sb2[o], b1v = sb2[o + 1];
                    simf[cA * 68 + o]     = dF[mt][nt][0] + b0v;
                    simf[cA * 68 + o + 1] = dF[mt][nt][1] + b1v;
                    simf[cB * 68 + o]     = dF[mt][nt][2] + b0v;
                    simf[cB * 68 + o + 1] = dF[mt][nt][3] + b1v;
                }
            }
        }
        BARH();

        {
            int o = th >> 2, q = th & 3;
            const float* sp = (const float*)(smem + OSIM) + (q * 16) * 68 + o;
            float mx = -3.4e38f;
#pragma unroll
            for (int k = 0; k < 16; ++k) mx = fmaxf(mx, sp[k * 68]);
            float vg[16];
#pragma unroll
            for (int k = 0; k < 16; ++k) {
                int j = sj[q * 16 + k];
                vg[k] = __ldg(g_qkv + ((size_t)(b * NN + j)) * 192 + 128 + o)
                      + __ldg(g_pe + ((size_t)b * 65536 + (size_t)n0 * 16 + q * 16 + k) * 64 + o);
            }
            float s = 0.f, a = 0.f;
#pragma unroll
            for (int k = 0; k < 16; ++k) {
                float e = __expf(sp[k * 68] - mx);
                s += e;
                a = fmaf(e, vg[k], a);
            }
            out[((size_t)(b * 64 + o)) * NN + n0 + q] = a / s;
        }
        BARH();
    }
#undef BARH
}

// ---------------------------------------------------------------------------
extern "C" void kernel_launch(void* const* d_in, const int* in_sizes, int n_in,
                              void* d_out, int out_size) {
    (void)in_sizes; (void)n_in; (void)out_size;
    const float* xyz    = (const float*)d_in[0];
    const float* points = (const float*)d_in[1];
    const float* w_qkv  = (const float*)d_in[2];
    const float* w_pos1 = (const float*)d_in[3];
    const float* b_pos1 = (const float*)d_in[4];
    const float* w_pos2 = (const float*)d_in[5];
    const float* b_pos2 = (const float*)d_in[6];
    const float* w_att1 = (const float*)d_in[7];
    const float* b_att1 = (const float*)d_in[8];
    const float* w_att2 = (const float*)d_in[9];
    const float* b_att2 = (const float*)d_in[10];
    float* out = (float*)d_out;

    cudaFuncSetAttribute(knn_qkv_kernel, cudaFuncAttributeMaxDynamicSharedMemorySize, 65536);
    cudaFuncSetAttribute(pos_kernel, cudaFuncAttributeMaxDynamicSharedMemorySize, SMEM_POS);
    cudaFuncSetAttribute(fused_mma_kernel, cudaFuncAttributeMaxDynamicSharedMemorySize, SMEM_TC);

    knn_qkv_kernel<<<768, 256, 65536>>>(xyz, points, w_qkv);
    pos_kernel<<<BB * NN * KK / 256, 256, SMEM_POS>>>(xyz, w_pos1, b_pos1, w_pos2, b_pos2);
    fused_mma_kernel<<<BB * (NN / 16), 512, SMEM_TC>>>(w_att1, b_att1, w_att2, b_att2, out);
}

// round 14
// speedup vs baseline: 1.2752x; 1.2752x over previous
#include <cuda_runtime.h>
#include <cuda_bf16.h>
#include <math.h>

#define BB 4
#define NN 4096
#define KK 16

typedef unsigned long long ull;
typedef unsigned int uint;

// scratch (device globals: allocation-free per harness rules)
__device__ float g_qkv[BB * NN * 192];            // point-major: [b][n][192]
__device__ int   g_idx[BB * NN * KK];             // [b][n][k]
__device__ float g_pe[(size_t)BB * NN * KK * 64]; // [gp][64]

// ============================ mma.sync helpers =============================
__device__ __forceinline__ uint smem_u32(const void* p) {
    uint a;
    asm("{ .reg .u64 t; cvta.to.shared.u64 t, %1; cvt.u32.u64 %0, t; }"
        : "=r"(a) : "l"(p));
    return a;
}
__device__ __forceinline__ void ldsm4(uint* r, uint addr) {
    asm volatile("ldmatrix.sync.aligned.m8n8.x4.shared.b16 {%0,%1,%2,%3}, [%4];"
                 : "=r"(r[0]), "=r"(r[1]), "=r"(r[2]), "=r"(r[3]) : "r"(addr));
}
__device__ __forceinline__ void mma_bf16(float* d, const uint* a, const uint* b) {
    asm volatile(
        "mma.sync.aligned.m16n8k16.row.col.f32.bf16.bf16.f32 "
        "{%0,%1,%2,%3},{%4,%5,%6,%7},{%8,%9},{%0,%1,%2,%3};"
        : "+f"(d[0]), "+f"(d[1]), "+f"(d[2]), "+f"(d[3])
        : "r"(a[0]), "r"(a[1]), "r"(a[2]), "r"(a[3]), "r"(b[0]), "r"(b[1]));
}
__device__ __forceinline__ uint bf2(float a, float b) {
    unsigned short ha = __bfloat16_as_ushort(__float2bfloat16_rn(a));
    unsigned short hb = __bfloat16_as_ushort(__float2bfloat16_rn(b));
    return (uint)ha | ((uint)hb << 16);
}
__device__ __forceinline__ float bfres(float a) {
    return a - __bfloat162float(__float2bfloat16_rn(a));
}
// A-fragment ldmatrix.x4 address (16x16 tile at (row0, byte L0), row width W)
__device__ __forceinline__ uint afrag_addr(uint base, int W, int row0, int L0, int lane) {
    int row = row0 + (lane & 7) + ((lane >> 3) & 1) * 8;
    int l = L0 + (lane >> 4) * 16;
    return base + row * W + (l ^ ((row & 7) << 4));
}
// B-fragment ldmatrix.x4 address (two n-tiles n0..n0+15, k16 at byte L0)
__device__ __forceinline__ uint bfrag_addr(uint base, int W, int n0, int L0, int lane) {
    int row = n0 + (lane & 7) + (lane >> 4) * 8;
    int l = L0 + ((lane >> 3) & 1) * 16;
    return base + row * W + (l ^ ((row & 7) << 4));
}

// fused kernel smem byte offsets
#define OFF_W1H 0u        /* [256 r][64 k] bf16 swz, 32768 */
#define OFF_W1L 32768u
#define OFF_W2H 65536u    /* [64 o][256 k] bf16 swz, 32768 */
#define OFF_W2L 98304u
#define OFF_HALF0 131072u /* per-half region, 49152 each */
#define HALF_STRIDE 49152u
#define OFF_B1  229376u
#define OFF_B2  230400u
#define OFF_SJ  230656u   /* int[2][64] */
#define SMEM_TC 231168u

// pos kernel smem byte offsets
#define POFF_AH  0u
#define POFF_AL  32768u
#define POFF_WH  65536u
#define POFF_WL  73728u
#define POFF_WP1 81920u
#define POFF_BP1 82688u
#define POFF_BP2 82944u
#define SMEM_POS 83200u

// padded candidate index: one float4 pad per 1024 entries -> partitions land
// on distinct bank quads (banks 4p..4p+3), killing the 4-way LDS conflict.
#define C4IDX(m) ((m) + ((m) >> 10))

// ---------------------------------------------------------------------------
// Kernel 1: combined KNN (blocks 0..255) + QKV (blocks 256..511).
// KNN: R12 structure (4 partitions/query, parallel-select insert) with a
// padded conflict-free candidate array.
// ---------------------------------------------------------------------------
__device__ __forceinline__ void topk_insert(float d2, int m, float bd[16], int bi[16]) {
    bool p[16];
#pragma unroll
    for (int i = 0; i < 16; ++i) p[i] = d2 < bd[i];
#pragma unroll
    for (int i = 15; i > 0; --i) {
        bd[i] = p[i] ? (p[i - 1] ? bd[i - 1] : d2) : bd[i];
        bi[i] = p[i] ? (p[i - 1] ? bi[i - 1] : m) : bi[i];
    }
    if (p[0]) { bd[0] = d2; bi[0] = m; }
}

__global__ void knn_qkv_kernel(const float* __restrict__ xyz,
                               const float* __restrict__ points,
                               const float* __restrict__ w_qkv) {
    extern __shared__ float sm[];
    int t = threadIdx.x;  // 256

    if (blockIdx.x < 256) {
        // ================= KNN (R12 + padded layout) =================
        float4* c4 = (float4*)sm;          // 4100 float4 = 65600 B (padded)
        float* md = sm + 16400;            // 256*16 floats
        int* mi = (int*)(md + 4096);       // 256*16 ints

        int b = blockIdx.x >> 6;
        int tile = blockIdx.x & 63;
        const float* xb = xyz + (size_t)b * 3 * NN;

        for (int m = t; m < NN; m += 256) {
            float x = xb[m], y = xb[NN + m], z = xb[2 * NN + m];
            c4[C4IDX(m)] = make_float4(x, y, z, x * x + y * y + z * z);
        }
        __syncthreads();

        int q = tile * 64 + (t >> 2);
        int p = t & 3;
        float4 qc = c4[C4IDX(q)];
        float qx = qc.x, qy = qc.y, qz = qc.z, sqq = qc.w;

        float bd[16]; int bi[16];
#pragma unroll
        for (int i = 0; i < 16; ++i) { bd[i] = 3.4e38f; bi[i] = -1; }

        const float4* cp = c4 + C4IDX(p * 1024);  // contiguous within partition
        for (int i = 0; i < 1024; i += 2) {
            float4 ca = cp[i], cb = cp[i + 1];
            float dot0 = fmaf(qx, ca.x, fmaf(qy, ca.y, qz * ca.z));
            float dot1 = fmaf(qx, cb.x, fmaf(qy, cb.y, qz * cb.z));
            float d20 = fmaf(-2.f, dot0, sqq + ca.w);
            float d21 = fmaf(-2.f, dot1, sqq + cb.w);
            int m = p * 1024 + i;
            if (d20 < bd[15]) topk_insert(d20, m, bd, bi);
            if (d21 < bd[15]) topk_insert(d21, m + 1, bd, bi);
        }
#pragma unroll
        for (int i = 0; i < 16; ++i) { md[t * 16 + i] = bd[i]; mi[t * 16 + i] = bi[i]; }
        __syncthreads();

        if (p == 0) {
            for (int src = 1; src < 4; ++src) {
                int base = (t + src) * 16;
                for (int e = 0; e < 16; ++e) {
                    float d2 = md[base + e];
                    if (d2 >= bd[15]) break;
                    topk_insert(d2, mi[base + e], bd, bi);
                }
            }
            int* op = g_idx + ((size_t)(b * NN + q)) * KK;
#pragma unroll
            for (int i = 0; i < 16; ++i) op[i] = bi[i];
        }
    } else {
        // ================= QKV (R8-verified version) =================
        int bid = blockIdx.x - 256;
        float* sw = sm;
        {
            const float4* a = (const float4*)w_qkv;
            float4* d = (float4*)sw;
            for (int i = t; i < 3072; i += 256) d[i] = a[i];
        }
        __syncthreads();
        int b = bid >> 6;
        int n = ((bid & 63) << 6) + (t & 63);
        int oh = t >> 6;

        float4 p4[16];
        const float* pb = points + (size_t)b * 64 * NN + n;
#pragma unroll
        for (int d4 = 0; d4 < 16; ++d4) {
            p4[d4].x = pb[(size_t)(4 * d4 + 0) * NN];
            p4[d4].y = pb[(size_t)(4 * d4 + 1) * NN];
            p4[d4].z = pb[(size_t)(4 * d4 + 2) * NN];
            p4[d4].w = pb[(size_t)(4 * d4 + 3) * NN];
        }
        float* outp = g_qkv + ((size_t)(b * NN + n)) * 192 + oh * 48;
        const float* swh = sw + oh * 48 * 64;
        for (int ob = 0; ob < 12; ++ob) {
            float a0 = 0.f, a1 = 0.f, a2 = 0.f, a3 = 0.f;
            const float4* w0 = (const float4*)(swh + (4 * ob + 0) * 64);
            const float4* w1 = (const float4*)(swh + (4 * ob + 1) * 64);
            const float4* w2 = (const float4*)(swh + (4 * ob + 2) * 64);
            const float4* w3 = (const float4*)(swh + (4 * ob + 3) * 64);
#pragma unroll
            for (int d4 = 0; d4 < 16; ++d4) {
                float4 pv = p4[d4];
                float4 wa = w0[d4], wb = w1[d4], wc = w2[d4], wd = w3[d4];
                a0 = fmaf(wa.x, pv.x, a0); a0 = fmaf(wa.y, pv.y, a0);
                a0 = fmaf(wa.z, pv.z, a0); a0 = fmaf(wa.w, pv.w, a0);
                a1 = fmaf(wb.x, pv.x, a1); a1 = fmaf(wb.y, pv.y, a1);
                a1 = fmaf(wb.z, pv.z, a1); a1 = fmaf(wb.w, pv.w, a1);
                a2 = fmaf(wc.x, pv.x, a2); a2 = fmaf(wc.y, pv.y, a2);
                a2 = fmaf(wc.z, pv.z, a2); a2 = fmaf(wc.w, pv.w, a2);
                a3 = fmaf(wd.x, pv.x, a3); a3 = fmaf(wd.y, pv.y, a3);
                a3 = fmaf(wd.z, pv.z, a3); a3 = fmaf(wd.w, pv.w, a3);
            }
            *(float4*)(outp + 4 * ob) = make_float4(a0, a1, a2, a3);
        }
    }
}

// ---------------------------------------------------------------------------
// Kernel 3: pos-MLP -> g_pe (unchanged — verified).
// ---------------------------------------------------------------------------
__global__ void __launch_bounds__(256, 2)
pos_kernel(const float* __restrict__ xyz,
           const float* __restrict__ w_pos1, const float* __restrict__ b_pos1,
           const float* __restrict__ w_pos2, const float* __restrict__ b_pos2) {
    extern __shared__ char psm[];
    uint sbase = smem_u32(psm);
    int t = threadIdx.x, wid = t >> 5, lane = t & 31;
    float* wp1 = (float*)(psm + POFF_WP1);
    float* bp1 = (float*)(psm + POFF_BP1);
    float* bp2 = (float*)(psm + POFF_BP2);

    for (int i = t; i < 1024; i += 256) {
        float4 f = ((const float4*)w_pos2)[i];
        int o = i >> 4, h = (i * 4) & 63;
        int swl = (h * 2) ^ ((o & 7) << 4);
        *(uint*)(psm + POFF_WH + o * 128 + swl)     = bf2(f.x, f.y);
        *(uint*)(psm + POFF_WH + o * 128 + swl + 4) = bf2(f.z, f.w);
        *(uint*)(psm + POFF_WL + o * 128 + swl)     = bf2(bfres(f.x), bfres(f.y));
        *(uint*)(psm + POFF_WL + o * 128 + swl + 4) = bf2(bfres(f.z), bfres(f.w));
    }
    if (t < 192) wp1[t] = w_pos1[t];
    if (t < 64) { bp1[t] = b_pos1[t]; bp2[t] = b_pos2[t]; }

    size_t gp0 = (size_t)blockIdx.x * 256;
    int b = (int)(gp0 >> 16);

    {
        size_t gp = gp0 + t;
        int n = (int)((gp >> 4) & 4095);
        int j = g_idx[gp];
        const float* xb = xyz + (size_t)b * 3 * NN;
        float gx0 = xb[n] - xb[j];
        float gx1 = xb[NN + n] - xb[NN + j];
        float gx2 = xb[2 * NN + n] - xb[2 * NN + j];
        __syncthreads();
        int rowb = t * 128;
        int sx = (t & 7) << 4;
#pragma unroll
        for (int h = 0; h < 64; h += 2) {
            float v0 = fmaf(wp1[h * 3 + 2], gx2,
                       fmaf(wp1[h * 3 + 1], gx1,
                       fmaf(wp1[h * 3 + 0], gx0, bp1[h])));
            float v1 = fmaf(wp1[h * 3 + 5], gx2,
                       fmaf(wp1[h * 3 + 4], gx1,
                       fmaf(wp1[h * 3 + 3], gx0, bp1[h + 1])));
            v0 = fmaxf(v0, 0.f); v1 = fmaxf(v1, 0.f);
            int swl = (h * 2) ^ sx;
            *(uint*)(psm + POFF_AH + rowb + swl) = bf2(v0, v1);
            *(uint*)(psm + POFF_AL + rowb + swl) = bf2(bfres(v0), bfres(v1));
        }
    }
    __syncthreads();

    {
        int p0 = wid * 32;
        float d[2][8][4];
#pragma unroll
        for (int mt = 0; mt < 2; ++mt)
#pragma unroll
            for (int nt = 0; nt < 8; ++nt)
#pragma unroll
                for (int e = 0; e < 4; ++e) d[mt][nt][e] = 0.f;

#pragma unroll
        for (int ks = 0; ks < 4; ++ks) {
            int L0 = ks * 32;
            uint aH[2][4], aL[2][4], bH[4][4], bL[4][4];
            ldsm4(aH[0], afrag_addr(sbase + POFF_AH, 128, p0, L0, lane));
            ldsm4(aH[1], afrag_addr(sbase + POFF_AH, 128, p0 + 16, L0, lane));
            ldsm4(aL[0], afrag_addr(sbase + POFF_AL, 128, p0, L0, lane));
            ldsm4(aL[1], afrag_addr(sbase + POFF_AL, 128, p0 + 16, L0, lane));
#pragma unroll
            for (int g = 0; g < 4; ++g) {
                ldsm4(bH[g], bfrag_addr(sbase + POFF_WH, 128, g * 16, L0, lane));
                ldsm4(bL[g], bfrag_addr(sbase + POFF_WL, 128, g * 16, L0, lane));
            }
#pragma unroll
            for (int mt = 0; mt < 2; ++mt)
#pragma unroll
                for (int nt = 0; nt < 8; ++nt) {
                    const uint* bh = &bH[nt >> 1][(nt & 1) * 2];
                    const uint* bl = &bL[nt >> 1][(nt & 1) * 2];
                    mma_bf16(d[mt][nt], aH[mt], bh);
                    mma_bf16(d[mt][nt], aH[mt], bl);
                    mma_bf16(d[mt][nt], aL[mt], bh);
                }
        }
#pragma unroll
        for (int mt = 0; mt < 2; ++mt) {
            int cA = p0 + mt * 16 + (lane >> 2);
            int cB = cA + 8;
#pragma unroll
            for (int nt = 0; nt < 8; ++nt) {
                int o = nt * 8 + (lane & 3) * 2;
                float b0v = bp2[o], b1v = bp2[o + 1];
                *(float2*)(g_pe + (gp0 + cA) * 64 + o) =
                    make_float2(d[mt][nt][0] + b0v, d[mt][nt][1] + b1v);
                *(float2*)(g_pe + (gp0 + cB) * 64 + o) =
                    make_float2(d[mt][nt][2] + b0v, d[mt][nt][3] + b1v);
            }
        }
    }
}

// ---------------------------------------------------------------------------
// Kernel 4: fused att-MLP via mma.sync — split-block; 4 sub-tiles/half
// (amortizes 128KB weight prologue; grid 512).
// ---------------------------------------------------------------------------
__global__ void __launch_bounds__(512, 1)
fused_mma_kernel(const float* __restrict__ w_att1, const float* __restrict__ b_att1,
                 const float* __restrict__ w_att2, const float* __restrict__ b_att2,
                 float* __restrict__ out) {
    extern __shared__ char smem[];
    uint sbase = smem_u32(smem);
    int t = threadIdx.x, wid = t >> 5, lane = t & 31;
    float* sb1 = (float*)(smem + OFF_B1);
    float* sb2 = (float*)(smem + OFF_B2);

    for (int i = t; i < 4096; i += 512) {       // w1 [256][64]
        float4 f = ((const float4*)w_att1)[i];
        int r = i >> 4, k = (i * 4) & 63;
        int swl = ((k * 2) ^ ((r & 7) << 4));
        *(uint*)(smem + OFF_W1H + r * 128 + swl)     = bf2(f.x, f.y);
        *(uint*)(smem + OFF_W1H + r * 128 + swl + 4) = bf2(f.z, f.w);
        *(uint*)(smem + OFF_W1L + r * 128 + swl)     = bf2(bfres(f.x), bfres(f.y));
        *(uint*)(smem + OFF_W1L + r * 128 + swl + 4) = bf2(bfres(f.z), bfres(f.w));
    }
    for (int i = t; i < 4096; i += 512) {       // w2 [64][256]
        float4 f = ((const float4*)w_att2)[i];
        int o = i >> 6, k = (i * 4) & 255;
        int swl = ((k * 2) ^ ((o & 7) << 4));
        *(uint*)(smem + OFF_W2H + o * 512 + swl)     = bf2(f.x, f.y);
        *(uint*)(smem + OFF_W2H + o * 512 + swl + 4) = bf2(f.z, f.w);
        *(uint*)(smem + OFF_W2L + o * 512 + swl)     = bf2(bfres(f.x), bfres(f.y));
        *(uint*)(smem + OFF_W2L + o * 512 + swl + 4) = bf2(bfres(f.z), bfres(f.w));
    }
    if (t < 256) sb1[t] = b_att1[t];
    if (t < 64) sb2[t] = b_att2[t];
    __syncthreads();

    const int half = wid >> 3;
    const int th = t & 255;
    const int wh = wid & 7;
    const uint HB = OFF_HALF0 + (uint)half * HALF_STRIDE;
    const uint OXH = HB, OXL = HB + 8192u, OHH = HB + 16384u, OHL = HB + 32768u;
    const uint OSIM = HB + 16384u;
    int* sj = (int*)(smem + OFF_SJ) + half * 64;

    const int c0 = (wh & 1) * 32;
    const int r0w = (wh >> 1) * 32;
    const int o0 = (wh >> 1) * 16;

    int b = blockIdx.x >> 7;                      // 128 blocks per batch
    int nb = ((blockIdx.x & 127) << 5) + half * 16;  // 32 queries per block

#define BARH() asm volatile("bar.sync %0, 256;" :: "r"(half + 1) : "memory")

    for (int st = 0; st < 4; ++st) {
        int n0 = nb + st * 4;

        {
            int c = th >> 2;
            int dq = (th & 3) << 4;
            int qi = c >> 4;
            int j = g_idx[((size_t)(b * NN + n0 + qi)) * KK + (c & 15)];
            if ((th & 3) == 0) sj[c] = j;
            const float* kp = g_qkv + ((size_t)(b * NN + j)) * 192 + 64 + dq;
            const float* qp = g_qkv + ((size_t)(b * NN + n0 + qi)) * 192 + dq;
            const float* pp = g_pe + ((size_t)b * 65536 + (size_t)n0 * 16 + c) * 64 + dq;
            int rowb = c * 128;
            int sx = (c & 7) << 4;
#pragma unroll
            for (int i = 0; i < 4; ++i) {
                float4 kk = *(const float4*)(kp + 4 * i);
                float4 qq = *(const float4*)(qp + 4 * i);
                float4 pe = *(const float4*)(pp + 4 * i);
                float x0 = qq.x - kk.x + pe.x;
                float x1 = qq.y - kk.y + pe.y;
                float x2 = qq.z - kk.z + pe.z;
                float x3 = qq.w - kk.w + pe.w;
                int swl = ((dq + 4 * i) * 2) ^ sx;
                *(uint*)(smem + OXH + rowb + swl)     = bf2(x0, x1);
                *(uint*)(smem + OXH + rowb + swl + 4) = bf2(x2, x3);
                *(uint*)(smem + OXL + rowb + swl)     = bf2(bfres(x0), bfres(x1));
                *(uint*)(smem + OXL + rowb + swl + 4) = bf2(bfres(x2), bfres(x3));
            }
        }
        BARH();

        float dF[2][2][4];
#pragma unroll
        for (int mt = 0; mt < 2; ++mt)
#pragma unroll
            for (int nt = 0; nt < 2; ++nt)
#pragma unroll
                for (int e = 0; e < 4; ++e) dF[mt][nt][e] = 0.f;

        for (int ph = 0; ph < 2; ++ph) {
            float dE[2][4][4];
#pragma unroll
            for (int mt = 0; mt < 2; ++mt)
#pragma unroll
                for (int nt = 0; nt < 4; ++nt)
#pragma unroll
                    for (int e = 0; e < 4; ++e) dE[mt][nt][e] = 0.f;

            int nbse = ph * 128 + r0w;
#pragma unroll
            for (int ks = 0; ks < 4; ++ks) {
                int L0 = ks * 32;
                uint aH[2][4], aL[2][4], bH[2][4], bL[2][4];
                ldsm4(aH[0], afrag_addr(sbase + OXH, 128, c0, L0, lane));
                ldsm4(aH[1], afrag_addr(sbase + OXH, 128, c0 + 16, L0, lane));
                ldsm4(aL[0], afrag_addr(sbase + OXL, 128, c0, L0, lane));
                ldsm4(aL[1], afrag_addr(sbase + OXL, 128, c0 + 16, L0, lane));
                ldsm4(bH[0], bfrag_addr(sbase + OFF_W1H, 128, nbse, L0, lane));
                ldsm4(bH[1], bfrag_addr(sbase + OFF_W1H, 128, nbse + 16, L0, lane));
                ldsm4(bL[0], bfrag_addr(sbase + OFF_W1L, 128, nbse, L0, lane));
                ldsm4(bL[1], bfrag_addr(sbase + OFF_W1L, 128, nbse + 16, L0, lane));
#pragma unroll
                for (int mt = 0; mt < 2; ++mt)
#pragma unroll
                    for (int nt = 0; nt < 4; ++nt) {
                        const uint* bh = &bH[nt >> 1][(nt & 1) * 2];
                        const uint* bl = &bL[nt >> 1][(nt & 1) * 2];
                        mma_bf16(dE[mt][nt], aH[mt], bh);
                        mma_bf16(dE[mt][nt], aH[mt], bl);
                        mma_bf16(dE[mt][nt], aL[mt], bh);
                    }
            }
#pragma unroll
            for (int mt = 0; mt < 2; ++mt) {
                int cA = c0 + mt * 16 + (lane >> 2);
                int cB = cA + 8;
#pragma unroll
                for (int nt = 0; nt < 4; ++nt) {
                    int rl = r0w + nt * 8 + (lane & 3) * 2;
                    int rg = ph * 128 + rl;
                    float b0v = sb1[rg], b1v = sb1[rg + 1];
                    float v0 = fmaxf(dE[mt][nt][0] + b0v, 0.f);
                    float v1 = fmaxf(dE[mt][nt][1] + b1v, 0.f);
                    float v2 = fmaxf(dE[mt][nt][2] + b0v, 0.f);
                    float v3 = fmaxf(dE[mt][nt][3] + b1v, 0.f);
                    int lA = (rl * 2) ^ ((cA & 7) << 4);
                    int lB = (rl * 2) ^ ((cB & 7) << 4);
                    *(uint*)(smem + OHH + cA * 256 + lA) = bf2(v0, v1);
                    *(uint*)(smem + OHL + cA * 256 + lA) = bf2(bfres(v0), bfres(v1));
                    *(uint*)(smem + OHH + cB * 256 + lB) = bf2(v2, v3);
                    *(uint*)(smem + OHL + cB * 256 + lB) = bf2(bfres(v2), bfres(v3));
                }
            }
            BARH();

#pragma unroll
            for (int ks = 0; ks < 8; ++ks) {
                int L0 = ks * 32;
                int L0w = ph * 256 + L0;
                uint aH[2][4], aL[2][4], bH[4], bL[4];
                ldsm4(aH[0], afrag_addr(sbase + OHH, 256, c0, L0, lane));
                ldsm4(aH[1], afrag_addr(sbase + OHH, 256, c0 + 16, L0, lane));
                ldsm4(aL[0], afrag_addr(sbase + OHL, 256, c0, L0, lane));
                ldsm4(aL[1], afrag_addr(sbase + OHL, 256, c0 + 16, L0, lane));
                ldsm4(bH, bfrag_addr(sbase + OFF_W2H, 512, o0, L0w, lane));
                ldsm4(bL, bfrag_addr(sbase + OFF_W2L, 512, o0, L0w, lane));
#pragma unroll
                for (int mt = 0; mt < 2; ++mt)
#pragma unroll
                    for (int nt = 0; nt < 2; ++nt) {
                        const uint* bh = &bH[nt * 2];
                        const uint* bl = &bL[nt * 2];
                        mma_bf16(dF[mt][nt], aH[mt], bh);
                        mma_bf16(dF[mt][nt], aH[mt], bl);
                        mma_bf16(dF[mt][nt], aL[mt], bh);
                    }
            }
            BARH();
        }

        {
            float* simf = (float*)(smem + OSIM);
#pragma unroll
            for (int mt = 0; mt < 2; ++mt) {
                int cA = c0 + mt * 16 + (lane >> 2);
                int cB = cA + 8;
#pragma unroll
                for (int nt = 0; nt < 2; ++nt) {
                    int o = o0 + nt * 8 + (lane & 3) * 2;
                    float b0v = sb2[o], b1v = sb2[o + 1];
                    simf[cA * 68 + o]     = dF[mt][nt][0] + b0v;
                    simf[cA * 68 + o + 1] = dF[mt][nt][1] + b1v;
                    simf[cB * 68 + o]     = dF[mt][nt][2] + b0v;
                    simf[cB * 68 + o + 1] = dF[mt][nt][3] + b1v;
                }
            }
        }
        BARH();

        {
            int o = th >> 2, q = th & 3;
            const float* sp = (const float*)(smem + OSIM) + (q * 16) * 68 + o;
            float mx = -3.4e38f;
#pragma unroll
            for (int k = 0; k < 16; ++k) mx = fmaxf(mx, sp[k * 68]);
            float vg[16];
#pragma unroll
            for (int k = 0; k < 16; ++k) {
                int j = sj[q * 16 + k];
                vg[k] = __ldg(g_qkv + ((size_t)(b * NN + j)) * 192 + 128 + o)
                      + __ldg(g_pe + ((size_t)b * 65536 + (size_t)n0 * 16 + q * 16 + k) * 64 + o);
            }
            float s = 0.f, a = 0.f;
#pragma unroll
            for (int k = 0; k < 16; ++k) {
                float e = __expf(sp[k * 68] - mx);
                s += e;
                a = fmaf(e, vg[k], a);
            }
            out[((size_t)(b * 64 + o)) * NN + n0 + q] = a / s;
        }
        BARH();
    }
#undef BARH
}

// ---------------------------------------------------------------------------
extern "C" void kernel_launch(void* const* d_in, const int* in_sizes, int n_in,
                              void* d_out, int out_size) {
    (void)in_sizes; (void)n_in; (void)out_size;
    const float* xyz    = (const float*)d_in[0];
    const float* points = (const float*)d_in[1];
    const float* w_qkv  = (const float*)d_in[2];
    const float* w_pos1 = (const float*)d_in[3];
    const float* b_pos1 = (const float*)d_in[4];
    const float* w_pos2 = (const float*)d_in[5];
    const float* b_pos2 = (const float*)d_in[6];
    const float* w_att1 = (const float*)d_in[7];
    const float* b_att1 = (const float*)d_in[8];
    const float* w_att2 = (const float*)d_in[9];
    const float* b_att2 = (const float*)d_in[10];
    float* out = (float*)d_out;

    cudaFuncSetAttribute(knn_qkv_kernel, cudaFuncAttributeMaxDynamicSharedMemorySize, 98368);
    cudaFuncSetAttribute(pos_kernel, cudaFuncAttributeMaxDynamicSharedMemorySize, SMEM_POS);
    cudaFuncSetAttribute(fused_mma_kernel, cudaFuncAttributeMaxDynamicSharedMemorySize, SMEM_TC);

    knn_qkv_kernel<<<512, 256, 98368>>>(xyz, points, w_qkv);
    pos_kernel<<<BB * NN * KK / 256, 256, SMEM_POS>>>(xyz, w_pos1, b_pos1, w_pos2, b_pos2);
    fused_mma_kernel<<<BB * (NN / 32), 512, SMEM_TC>>>(w_att1, b_att1, w_att2, b_att2, out);
}